// round 7
// baseline (speedup 1.0000x reference)
#include <cuda_runtime.h>
#include <cuda_bf16.h>
#include <cstdint>
#include <math.h>

#define BB 4
#define NN 1024
#define PP 42
#define DD 96
#define PD 4032          // PP*DD
#define KNODE 8
#define KCAND 12         // prepass candidates (margin over 8)
#define KTOK 8
#define POUT 50          // PP + KTOK
#define EPSD 1e-7

#define NEG_INF __int_as_float(0xff800000)
#define NEG_INF_D (-1.0e300)

// ---------------- scratch (device globals; no allocation) ----------------
__device__ float  g_sim[BB * NN * NN];        // prepass dots (fp32 out of mma)
__device__ __align__(16) __nv_bfloat16 g_hbf[BB * NN * PD];  // bf16 copy of h
__device__ double g_inv_node_d[BB * NN];
__device__ float  g_inv_node_f[BB * NN];
__device__ double g_inv_tok_d[BB * NN * PP];
__device__ int    g_cand[BB * NN * KCAND];    // prepass top-12
__device__ int    g_sel[BB * NN * KTOK];      // selected tokens: m*64 + p

// ---------------- compensated arithmetic helpers --------------------------
__device__ __forceinline__ void two_sum(float a, float b, float& s, float& e) {
    s = a + b;
    float z = s - a;
    e = (a - (s - z)) + (b - z);
}
__device__ __forceinline__ void dot2_step(float a, float b, float& hi, float& lo) {
    float p = a * b;
    float ep = fmaf(a, b, -p);
    float s, e;
    two_sum(hi, p, s, e);
    hi = s;
    lo += e + ep;
}

__device__ __forceinline__ void cp16(uint32_t s, const void* g) {
    asm volatile("cp.async.cg.shared.global [%0], [%1], 16;\n" :: "r"(s), "l"(g));
}

// ---------------- packed f32x2 helpers (Blackwell FFMA2) ------------------
__device__ __forceinline__ unsigned long long pk2(float lo, float hi) {
    unsigned long long r;
    asm("mov.b64 %0, {%1, %2};" : "=l"(r) : "f"(lo), "f"(hi));
    return r;
}
__device__ __forceinline__ void fma2(unsigned long long& d,
                                     unsigned long long a, unsigned long long b) {
    asm("fma.rn.f32x2 %0, %1, %2, %0;" : "+l"(d) : "l"(a), "l"(b));
}
__device__ __forceinline__ void upk2(unsigned long long v, float& lo, float& hi) {
    asm("mov.b64 {%0, %1}, %2;" : "=f"(lo), "=f"(hi) : "l"(v));
}

// =========================================================================
// K1: FUSED bf16 conversion + exact token/node norms.  One block per bn,
// 128 threads.  h row is read once (conversion pass warms L1 for norms).
// =========================================================================
__global__ __launch_bounds__(128) void k_convnorm(const float* __restrict__ h) {
    int bn = blockIdx.x;
    const float* base = h + (size_t)bn * PD;
    __shared__ double s_node[4];
    int t = threadIdx.x, warp = t >> 5, lane = t & 31;

    // bf16 conversion (float4 -> bf16x4)
    const float4* b4 = (const float4*)base;
    uint2* o2 = (uint2*)(g_hbf + (size_t)bn * PD);
    for (int i = t; i < PD / 4; i += 128) {
        float4 v = b4[i];
        __nv_bfloat162 lo = __floats2bfloat162_rn(v.x, v.y);
        __nv_bfloat162 hi = __floats2bfloat162_rn(v.z, v.w);
        uint2 pkv;
        pkv.x = *(uint32_t*)&lo;
        pkv.y = *(uint32_t*)&hi;
        o2[i] = pkv;
    }

    // norms (compensated fp32 -> fp64)
    double nodesum = 0.0;
    for (int p = warp; p < PP; p += 4) {
        const float* tp = base + p * DD;
        float hi = 0.f, lo = 0.f;
        float v0 = tp[lane], v1 = tp[lane + 32], v2 = tp[lane + 64];
        dot2_step(v0, v0, hi, lo);
        dot2_step(v1, v1, hi, lo);
        dot2_step(v2, v2, hi, lo);
        double s = (double)hi + (double)lo;
        #pragma unroll
        for (int o = 16; o; o >>= 1) s += __shfl_xor_sync(0xffffffffu, s, o);
        if (lane == 0) g_inv_tok_d[bn * PP + p] = 1.0 / (sqrt(s) + EPSD);
        nodesum += s;
    }
    if (lane == 0) s_node[warp] = nodesum;
    __syncthreads();
    if (t == 0) {
        double tt = s_node[0] + s_node[1] + s_node[2] + s_node[3];
        double inv = 1.0 / (sqrt(tt) + EPSD);
        g_inv_node_d[bn] = inv;
        g_inv_node_f[bn] = (float)inv;
    }
}

// =========================================================================
// K2: bf16 tensor-core prepass GEMM (symmetric, upper tiles + mirror).
// =========================================================================
__global__ void __launch_bounds__(256, 2) k_sim_mma() {
    if (blockIdx.y > blockIdx.x) return;
    extern __shared__ __align__(16) unsigned char smraw[];
    const int t = threadIdx.x;
    const int lane = t & 31, warp = t >> 5;
    const int warp_m = warp >> 2, warp_n = warp & 3;
    const int bz = blockIdx.z;
    const int rowBase = blockIdx.y * 128, colBase = blockIdx.x * 128;
    const __nv_bfloat16* base = g_hbf + (size_t)bz * NN * PD;
    uint32_t s0 = (uint32_t)__cvta_generic_to_shared(smraw);

    float acc[4][4][4];
    #pragma unroll
    for (int i = 0; i < 4; i++)
        #pragma unroll
        for (int j = 0; j < 4; j++)
            #pragma unroll
            for (int q = 0; q < 4; q++) acc[i][j][q] = 0.f;

    auto issue = [&](int it, int buf) {
        int k0 = it * 64;
        uint32_t sbuf = s0 + buf * 32768;
        #pragma unroll
        for (int i = 0; i < 4; i++) {
            int u = t + 256 * i;
            int r = u >> 3, c = u & 7;
            uint32_t soff = r * 128 + ((c ^ (r & 7)) << 4);
            cp16(sbuf + soff, base + (size_t)(rowBase + r) * PD + k0 + c * 8);
            cp16(sbuf + 16384 + soff, base + (size_t)(colBase + r) * PD + k0 + c * 8);
        }
        asm volatile("cp.async.commit_group;\n");
    };

    issue(0, 0);
    for (int it = 0; it < 63; it++) {
        if (it < 62) {
            issue(it + 1, (it + 1) & 1);
            asm volatile("cp.async.wait_group 1;\n");
        } else {
            asm volatile("cp.async.wait_group 0;\n");
        }
        __syncthreads();
        uint32_t sA = s0 + (it & 1) * 32768;
        uint32_t sB = sA + 16384;
        #pragma unroll
        for (int kk = 0; kk < 4; kk++) {
            uint32_t a[4][4], bf[4][2];
            #pragma unroll
            for (int mi = 0; mi < 4; mi++) {
                int row = warp_m * 64 + mi * 16 + ((lane >> 3) & 1) * 8 + (lane & 7);
                int ch = kk * 2 + (lane >> 4);
                uint32_t addr = sA + row * 128 + ((ch ^ (row & 7)) << 4);
                asm volatile("ldmatrix.sync.aligned.m8n8.x4.shared.b16 {%0,%1,%2,%3}, [%4];\n"
                    : "=r"(a[mi][0]), "=r"(a[mi][1]), "=r"(a[mi][2]), "=r"(a[mi][3]) : "r"(addr));
            }
            #pragma unroll
            for (int call = 0; call < 2; call++) {
                int row = warp_n * 32 + call * 16 + ((lane >> 4) & 1) * 8 + (lane & 7);
                int ch = kk * 2 + ((lane >> 3) & 1);
                uint32_t addr = sB + row * 128 + ((ch ^ (row & 7)) << 4);
                uint32_t r0, r1, r2, r3;
                asm volatile("ldmatrix.sync.aligned.m8n8.x4.shared.b16 {%0,%1,%2,%3}, [%4];\n"
                    : "=r"(r0), "=r"(r1), "=r"(r2), "=r"(r3) : "r"(addr));
                bf[call * 2][0] = r0; bf[call * 2][1] = r1;
                bf[call * 2 + 1][0] = r2; bf[call * 2 + 1][1] = r3;
            }
            #pragma unroll
            for (int mi = 0; mi < 4; mi++)
                #pragma unroll
                for (int ni = 0; ni < 4; ni++)
                    asm volatile("mma.sync.aligned.m16n8k16.row.col.f32.bf16.bf16.f32 "
                        "{%0,%1,%2,%3}, {%4,%5,%6,%7}, {%8,%9}, {%0,%1,%2,%3};\n"
                        : "+f"(acc[mi][ni][0]), "+f"(acc[mi][ni][1]),
                          "+f"(acc[mi][ni][2]), "+f"(acc[mi][ni][3])
                        : "r"(a[mi][0]), "r"(a[mi][1]), "r"(a[mi][2]), "r"(a[mi][3]),
                          "r"(bf[ni][0]), "r"(bf[ni][1]));
        }
        __syncthreads();
    }

    float* C = g_sim + (size_t)bz * NN * NN;
    const bool offdiag = (rowBase != colBase);
    #pragma unroll
    for (int mi = 0; mi < 4; mi++) {
        int r = rowBase + warp_m * 64 + mi * 16 + (lane >> 2);
        #pragma unroll
        for (int ni = 0; ni < 4; ni++) {
            int c = colBase + warp_n * 32 + ni * 8 + (lane & 3) * 2;
            *(float2*)(C + (size_t)r * NN + c) = make_float2(acc[mi][ni][0], acc[mi][ni][1]);
            *(float2*)(C + (size_t)(r + 8) * NN + c) = make_float2(acc[mi][ni][2], acc[mi][ni][3]);
            if (offdiag) {
                C[(size_t)c * NN + r]           = acc[mi][ni][0];
                C[(size_t)(c + 1) * NN + r]     = acc[mi][ni][1];
                C[(size_t)c * NN + r + 8]       = acc[mi][ni][2];
                C[(size_t)(c + 1) * NN + r + 8] = acc[mi][ni][3];
            }
        }
    }
}

// =========================================================================
// K3: prepass — normalize row, zero diag, select top-12 candidates.
// =========================================================================
__global__ __launch_bounds__(256) void k_topk_node() {
    int bn = blockIdx.x;
    int b = bn >> 10, n = bn & 1023;
    __shared__ float vals[NN];
    __shared__ float rv[256];
    __shared__ int   ri[256];
    int t = threadIdx.x;
    float invn = g_inv_node_f[bn];
    const float* row = g_sim + (size_t)b * NN * NN + (size_t)n * NN;
    for (int m = t; m < NN; m += 256) {
        vals[m] = (m == n) ? 0.f : row[m] * invn * g_inv_node_f[b * NN + m];
    }
    __syncthreads();
    for (int k = 0; k < KCAND; k++) {
        float bv = NEG_INF; int bi = 0;
        #pragma unroll
        for (int j = 0; j < 4; j++) {
            int m = t + j * 256;
            float v = vals[m];
            if (v > bv) { bv = v; bi = m; }
        }
        rv[t] = bv; ri[t] = bi;
        __syncthreads();
        if (t < 32) {
            float v = rv[t]; int i = ri[t];
            #pragma unroll
            for (int j = 1; j < 8; j++) {
                float v2 = rv[t + j * 32]; int i2 = ri[t + j * 32];
                if (v2 > v || (v2 == v && i2 < i)) { v = v2; i = i2; }
            }
            #pragma unroll
            for (int o = 16; o; o >>= 1) {
                float v2 = __shfl_xor_sync(0xffffffffu, v, o);
                int   i2 = __shfl_xor_sync(0xffffffffu, i, o);
                if (v2 > v || (v2 == v && i2 < i)) { v = v2; i = i2; }
            }
            if (t == 0) {
                g_cand[bn * KCAND + k] = i;
                vals[i] = NEG_INF;
            }
        }
        __syncthreads();
    }
}

// =========================================================================
// K4: FUSED selection — exact node re-rank (12 candidates, warp-per-cand)
// -> top-8 nodes; exact token cosine (336, per-thread) -> top-8 tokens;
// writes packed (m*64+p) to g_sel.  No W, no gather, ~22 KB smem.
// =========================================================================
__global__ __launch_bounds__(256) void k_tok_sel(const float* __restrict__ h) {
    __shared__ __align__(16) float sQ[PD];       // own node row (query)
    __shared__ double ssim[KNODE * PP];          // 336
    __shared__ double rvd[256];
    __shared__ int    ri[256];
    __shared__ double exd[KCAND];
    __shared__ int    scnd[KCAND];
    __shared__ int    snode[KNODE];

    int bn = blockIdx.x;
    int b = bn >> 10;
    int t = threadIdx.x, warp = t >> 5, lane = t & 31;

    // stage own flat row + candidates
    const float4* q4 = (const float4*)(h + (size_t)bn * PD);
    float4* sQ4 = (float4*)sQ;
    for (int i = t; i < PD / 4; i += 256) sQ4[i] = q4[i];
    if (t < KCAND) scnd[t] = g_cand[bn * KCAND + t];
    __syncthreads();

    // ---- exact node sims: warp per candidate (8 warps, 12 cands) ----
    for (int c = warp; c < KCAND; c += 8) {
        int m = scnd[c];
        const float4* f4 = (const float4*)(h + (size_t)(b * NN + m) * PD);
        float hx = 0.f, lx = 0.f, hy = 0.f, ly = 0.f;
        float hz = 0.f, lz = 0.f, hw = 0.f, lw = 0.f;
        #pragma unroll 4
        for (int j = 0; j < 31; j++) {
            int i4 = j * 32 + lane;
            float4 a = sQ4[i4];
            float4 cc = f4[i4];
            dot2_step(a.x, cc.x, hx, lx);
            dot2_step(a.y, cc.y, hy, ly);
            dot2_step(a.z, cc.z, hz, lz);
            dot2_step(a.w, cc.w, hw, lw);
        }
        if (lane < 16) {
            int i4 = 992 + lane;
            float4 a = sQ4[i4];
            float4 cc = f4[i4];
            dot2_step(a.x, cc.x, hx, lx);
            dot2_step(a.y, cc.y, hy, ly);
            dot2_step(a.z, cc.z, hz, lz);
            dot2_step(a.w, cc.w, hw, lw);
        }
        double v = ((double)hx + lx) + ((double)hy + ly) +
                   ((double)hz + lz) + ((double)hw + lw);
        #pragma unroll
        for (int o = 16; o; o >>= 1) v += __shfl_xor_sync(0xffffffffu, v, o);
        if (lane == 0) exd[c] = v * g_inv_node_d[bn] * g_inv_node_d[b * NN + m];
    }
    __syncthreads();

    if (t == 0) {
        unsigned used = 0;
        for (int k = 0; k < KNODE; k++) {
            int best = -1;
            for (int j = 0; j < KCAND; j++) {
                if (used & (1u << j)) continue;
                if (best < 0 || exd[j] > exd[best] ||
                    (exd[j] == exd[best] && scnd[j] < scnd[best])) best = j;
            }
            used |= (1u << best);
            snode[k] = scnd[best];
        }
    }
    __syncthreads();

    // ---- exact token sims: per-thread over 336 candidates ----
    double qinv = g_inv_tok_d[bn * PP + PP - 1];
    const float4* tq4 = (const float4*)(sQ + (PP - 1) * DD);
    for (int c = t; c < KNODE * PP; c += 256) {
        int kn = c / PP, p = c - kn * PP;
        int m = snode[kn];
        const float4* tp4 = (const float4*)(h + (((size_t)(b * NN + m)) * PP + p) * DD);
        float hx = 0.f, lx = 0.f, hy = 0.f, ly = 0.f;
        float hz = 0.f, lz = 0.f, hw = 0.f, lw = 0.f;
        #pragma unroll
        for (int j = 0; j < DD / 4; j++) {
            float4 a = tq4[j];
            float4 f = tp4[j];
            dot2_step(a.x, f.x, hx, lx);
            dot2_step(a.y, f.y, hy, ly);
            dot2_step(a.z, f.z, hz, lz);
            dot2_step(a.w, f.w, hw, lw);
        }
        double v = ((double)hx + lx) + ((double)hy + ly) +
                   ((double)hz + lz) + ((double)hw + lw);
        ssim[c] = v * qinv * g_inv_tok_d[(b * NN + m) * PP + p];
    }
    __syncthreads();

    // ---- exact top-8 of 336 ----
    for (int k = 0; k < KTOK; k++) {
        double bv = NEG_INF_D; int bi = 0;
        for (int c = t; c < KNODE * PP; c += 256) {
            double v = ssim[c];
            if (v > bv) { bv = v; bi = c; }
        }
        rvd[t] = bv; ri[t] = bi;
        __syncthreads();
        if (t < 32) {
            double v = rvd[t]; int i = ri[t];
            #pragma unroll
            for (int j = 1; j < 8; j++) {
                double v2 = rvd[t + j * 32]; int i2 = ri[t + j * 32];
                if (v2 > v || (v2 == v && i2 < i)) { v = v2; i = i2; }
            }
            #pragma unroll
            for (int o = 16; o; o >>= 1) {
                double v2 = __shfl_xor_sync(0xffffffffu, v, o);
                int    i2 = __shfl_xor_sync(0xffffffffu, i, o);
                if (v2 > v || (v2 == v && i2 < i)) { v = v2; i = i2; }
            }
            if (t == 0) {
                int c = i; int kn = c / PP, p = c - kn * PP;
                g_sel[bn * KTOK + k] = snode[kn] * 64 + p;
                ssim[c] = NEG_INF_D;
            }
        }
        __syncthreads();
    }
}

// =========================================================================
// K5: sk linear — gather 64 selected tokens/block, x @ W^T + b + nt ->
// out[:, :, 42:50, :].  f32x2 packed FFMA.
// =========================================================================
__global__ __launch_bounds__(256) void k_sklin(const float* __restrict__ h,
                                               const float* __restrict__ W,
                                               const float* __restrict__ bias,
                                               const float* __restrict__ ntok,
                                               float* __restrict__ out) {
    __shared__ __align__(16) float sXT[DD * 68];
    __shared__ __align__(16) float sWT[DD * 98];
    __shared__ size_t rowoff[64];

    int r0 = blockIdx.x * 64;                    // knn-token slot base
    int t = threadIdx.x;

    if (t < 64) {
        int rr = r0 + t;
        int bn = rr >> 3;
        int b = bn >> 10;
        int s = g_sel[bn * KTOK + (rr & 7)];
        int m = s >> 6, p = s & 63;
        rowoff[t] = (((size_t)(b * NN + m)) * PP + p) * (size_t)DD;
    }
    __syncthreads();

    for (int i = t; i < 64 * DD; i += 256) {
        int r = i / DD, d = i - r * DD;
        sXT[d * 68 + r] = h[rowoff[r] + d];
    }
    for (int i = t; i < DD * DD; i += 256) {
        int e = i / DD, d = i - e * DD;
        sWT[d * 98 + e] = W[i];
    }
    __syncthreads();

    float nt = ntok[0];
    int tx = t & 15, ty = t >> 4;
    unsigned long long acc[4][3];
    #pragma unroll
    for (int i = 0; i < 4; i++)
        #pragma unroll
        for (int j = 0; j < 3; j++)
            acc[i][j] = pk2(bias[tx * 6 + 2 * j] + nt, bias[tx * 6 + 2 * j + 1] + nt);

    #pragma unroll 4
    for (int d = 0; d < DD; d++) {
        float4 xv = *(const float4*)(sXT + d * 68 + ty * 4);
        const unsigned long long* wp = (const unsigned long long*)(sWT + d * 98 + tx * 6);
        unsigned long long b0 = wp[0], b1 = wp[1], b2 = wp[2];
        float x[4] = {xv.x, xv.y, xv.z, xv.w};
        #pragma unroll
        for (int i = 0; i < 4; i++) {
            unsigned long long a = pk2(x[i], x[i]);
            fma2(acc[i][0], a, b0);
            fma2(acc[i][1], a, b1);
            fma2(acc[i][2], a, b2);
        }
    }

    #pragma unroll
    for (int i = 0; i < 4; i++) {
        int rr = r0 + ty * 4 + i;
        int bn = rr >> 3, k = rr & 7;
        float* orow = out + (((size_t)bn) * POUT + PP + k) * (size_t)DD + tx * 6;
        #pragma unroll
        for (int j = 0; j < 3; j++) {
            float lo, hi;
            upk2(acc[i][j], lo, hi);
            orow[2 * j] = lo;
            orow[2 * j + 1] = hi;
        }
    }
}

// =========================================================================
// K6: hf = h @ W^T + b -> out[:, :, 0:42, :].  f32x2 packed FFMA.
// =========================================================================
__global__ __launch_bounds__(256) void k_hf(const float* __restrict__ h,
                                            const float* __restrict__ W,
                                            const float* __restrict__ bias,
                                            float* __restrict__ out) {
    extern __shared__ __align__(16) float dyn[];
    float* sXT = dyn;                 // [DD][68]
    float* sWT = dyn + DD * 68;       // [DD][98]

    int r0 = blockIdx.x * 64;
    int t = threadIdx.x;

    const float* Xbase = h + (size_t)r0 * DD;
    for (int i = t; i < 64 * DD; i += 256) {
        int r = i / DD, d = i - r * DD;
        sXT[d * 68 + r] = Xbase[i];
    }
    for (int i = t; i < DD * DD; i += 256) {
        int e = i / DD, d = i - e * DD;
        sWT[d * 98 + e] = W[i];
    }
    __syncthreads();

    int tx = t & 15, ty = t >> 4;
    unsigned long long acc[4][3];
    #pragma unroll
    for (int i = 0; i < 4; i++)
        #pragma unroll
        for (int j = 0; j < 3; j++)
            acc[i][j] = pk2(bias[tx * 6 + 2 * j], bias[tx * 6 + 2 * j + 1]);

    #pragma unroll 4
    for (int d = 0; d < DD; d++) {
        float4 xv = *(const float4*)(sXT + d * 68 + ty * 4);
        const unsigned long long* wp = (const unsigned long long*)(sWT + d * 98 + tx * 6);
        unsigned long long b0 = wp[0], b1 = wp[1], b2 = wp[2];
        float x[4] = {xv.x, xv.y, xv.z, xv.w};
        #pragma unroll
        for (int i = 0; i < 4; i++) {
            unsigned long long a = pk2(x[i], x[i]);
            fma2(acc[i][0], a, b0);
            fma2(acc[i][1], a, b1);
            fma2(acc[i][2], a, b2);
        }
    }

    #pragma unroll
    for (int i = 0; i < 4; i++) {
        int r = r0 + ty * 4 + i;
        int bn = r / PP, p = r - bn * PP;
        float* orow = out + (((size_t)bn) * POUT + p) * (size_t)DD + tx * 6;
        #pragma unroll
        for (int j = 0; j < 3; j++) {
            float lo, hi;
            upk2(acc[i][j], lo, hi);
            orow[2 * j] = lo;
            orow[2 * j + 1] = hi;
        }
    }
}

// =========================================================================
extern "C" void kernel_launch(void* const* d_in, const int* in_sizes, int n_in,
                              void* d_out, int out_size) {
    const float* h    = (const float*)d_in[0];
    const float* W    = (const float*)d_in[1];
    const float* bias = (const float*)d_in[2];
    const float* ntok = (const float*)d_in[3];
    float* out = (float*)d_out;

    k_convnorm<<<BB * NN, 128>>>(h);                                 // 1

    cudaFuncSetAttribute(k_sim_mma, cudaFuncAttributeMaxDynamicSharedMemorySize, 65536);
    dim3 g2(NN / 128, NN / 128, BB);
    k_sim_mma<<<g2, 256, 65536>>>();                                 // 2

    k_topk_node<<<BB * NN, 256>>>();                                 // 3

    k_tok_sel<<<BB * NN, 256>>>(h);                                  // 4  <- profiled slot

    k_sklin<<<(BB * NN * KTOK) / 64, 256>>>(h, W, bias, ntok, out);  // 5

    size_t hf_smem = (size_t)(DD * 68 + DD * 98) * sizeof(float);
    cudaFuncSetAttribute(k_hf, cudaFuncAttributeMaxDynamicSharedMemorySize, (int)hf_smem);
    k_hf<<<(BB * NN * PP) / 64, 256, hf_smem>>>(h, W, bias, out);    // 6
}